// round 9
// baseline (speedup 1.0000x reference)
#include <cuda_runtime.h>
#include <cuda_bf16.h>
#include <cstdint>

// Problem constants
#define NB   64      // batch
#define TT   512     // time steps
#define DD   512     // input dim
#define HH   512     // hidden dim
#define G3   1536    // 3*H

// Scratch (device globals: allocation-free)
// x in fragment-ready bf16 hi/lo layout: [n][t][kt(32)][tq(4)][4]
//   cell = { hi(k2), lo(k2), hi(k2+4), lo(k2+4) },  k2 = kt*8 + tq
__device__ unsigned g_xbf[(size_t)NB * TT * 512];     // 64 MB
// h in same fragment layout: [dir][par][row(64)][kt(32)][tq(4)][4]
__device__ unsigned g_hbf[2 * 2 * 64 * 512];
__device__ unsigned g_arrive[2];                      // monotonic barrier counters

__device__ __forceinline__ unsigned packbf(float odd_k, float even_k) {
    unsigned r;
    asm("cvt.rn.bf16x2.f32 %0, %1, %2;" : "=r"(r) : "f"(odd_k), "f"(even_k));
    return r;
}
__device__ __forceinline__ float bfres(float x) {
    return x - __bfloat162float(__float2bfloat16_rn(x));
}
__device__ __forceinline__ void mma_bf16(float* c, const unsigned* a,
                                         unsigned b0, unsigned b1) {
    asm volatile(
        "mma.sync.aligned.m16n8k16.row.col.f32.bf16.bf16.f32 "
        "{%0,%1,%2,%3}, {%4,%5,%6,%7}, {%8,%9}, {%0,%1,%2,%3};"
        : "+f"(c[0]), "+f"(c[1]), "+f"(c[2]), "+f"(c[3])
        : "r"(a[0]), "r"(a[1]), "r"(a[2]), "r"(a[3]), "r"(b0), "r"(b1));
}

// -----------------------------------------------------------------------------
// Init: zero bf16 h buffers + barrier counters
// -----------------------------------------------------------------------------
__global__ void init_kernel(unsigned* hbf) {
    int i = blockIdx.x * blockDim.x + threadIdx.x;   // 32768 uint4s
    reinterpret_cast<uint4*>(hbf)[i] = make_uint4(0u, 0u, 0u, 0u);
    if (i == 0) { g_arrive[0] = 0; g_arrive[1] = 0; }
}

// -----------------------------------------------------------------------------
// Convert x (fp32) -> fragment-ready bf16 hi/lo layout.
// Thread = one (m, kt): 16 consecutive k floats -> 4 uint4 cells.
// Grid: 32768*32/256 = 4096 blocks.
// -----------------------------------------------------------------------------
__global__ __launch_bounds__(256) void convert_x_kernel(
    const float* __restrict__ x, unsigned* __restrict__ xbf)
{
    const int idx = blockIdx.x * blockDim.x + threadIdx.x;
    const int m  = idx >> 5;
    const int kt = idx & 31;
    const float* src = x + (size_t)m * DD + kt * 16;
    float f[16];
#pragma unroll
    for (int q = 0; q < 4; q++) {
        const float4 v = reinterpret_cast<const float4*>(src)[q];
        f[4 * q] = v.x; f[4 * q + 1] = v.y; f[4 * q + 2] = v.z; f[4 * q + 3] = v.w;
    }
    unsigned* dst = xbf + (size_t)m * 512 + kt * 16;
#pragma unroll
    for (int tq = 0; tq < 4; tq++) {
        uint4 c;
        c.x = packbf(f[2 * tq + 1], f[2 * tq]);
        c.y = packbf(bfres(f[2 * tq + 1]), bfres(f[2 * tq]));
        c.z = packbf(f[2 * tq + 9], f[2 * tq + 8]);
        c.w = packbf(bfres(f[2 * tq + 9]), bfres(f[2 * tq + 8]));
        reinterpret_cast<uint4*>(dst)[tq] = c;
    }
}

// -----------------------------------------------------------------------------
// Fully-fused persistent BiGRU kernel.
// Grid dim3(64, 2), 256 threads. Block = (dir, 8 hidden cols -> 24 gate cols).
// Per step, per warp (split-K over 2 warp-halves):
//   x-part : 16 kt MMAs from g_xbf (static)   -- BEFORE the barrier wait
//   barrier: wait for step s-1 h writes
//   h-part : 16 kt MMAs from g_hbf
//   exchange + gates (z,r combined; gx/gh separate for reset gate) + writes
//   arrive (release)
// SMEM: W fragments [kt(64)][gate(3)][lane][4] = 96KB + red 8KB.
// -----------------------------------------------------------------------------
#define BFRAG_UINTS  (64 * 3 * 32 * 4)           // 24576 -> 96KB
#define REDF         (16 * 32 * 4)               // 2048 floats -> 8KB
#define PMMA_SMEM    ((BFRAG_UINTS + REDF) * 4)  // 106496 B
#define HB_PP        32768                       // uints per (dir,parity)

__global__ __launch_bounds__(256, 1) void gru_fused_kernel(
    const float* __restrict__ Wx_f, const float* __restrict__ Wh_f,
    const float* __restrict__ b_f,
    const float* __restrict__ Wx_b, const float* __restrict__ Wh_b,
    const float* __restrict__ b_b,
    const unsigned* __restrict__ xbf, unsigned* __restrict__ hbf,
    float* __restrict__ out)
{
    extern __shared__ unsigned smu[];
    unsigned* bfr = smu;                               // [kt64][gate3][lane][4]
    float* red = reinterpret_cast<float*>(smu + BFRAG_UINTS);

    const int dir = blockIdx.y;
    const int j0  = blockIdx.x * 8;
    const float* __restrict__ Wx   = dir ? Wx_b : Wx_f;
    const float* __restrict__ Wh   = dir ? Wh_b : Wh_f;
    const float* __restrict__ bias = dir ? b_b  : b_f;

    const int t  = threadIdx.x;
    const int w  = t >> 5;
    const int l  = t & 31;
    const int g  = l >> 2;
    const int tq = l & 3;
    const int mt = w & 3;
    const int khalf = w >> 2;

    // ---- fill W fragments once: reg 0 = Wx (kt 0..31), reg 1 = Wh (kt 32..63)
    for (int idx = t; idx < 12288; idx += 256) {
        const int reg   = idx / 6144;
        const int rem   = idx - reg * 6144;
        const int c_loc = rem >> 8;              // 0..23
        const int k2    = rem & 255;
        const int gate  = c_loc >> 3;
        const int jj    = c_loc & 7;
        const int col   = gate * HH + j0 + jj;
        const float* W  = reg ? Wh : Wx;
        const float e = W[(size_t)(2 * k2) * G3 + col];
        const float o = W[(size_t)(2 * k2 + 1) * G3 + col];
        const int kt = reg * 32 + (k2 >> 3);
        const int pp = k2 & 7;
        const int rr = pp >> 2;
        const int ts = pp & 3;
        const int off4 = ((kt * 3 + gate) * 32 + jj * 4 + ts) * 4;
        bfr[off4 + rr]     = packbf(o, e);
        bfr[off4 + 2 + rr] = packbf(bfres(o), bfres(e));
    }
    __syncthreads();

    const int row0 = mt * 16 + g;
    const int row1 = row0 + 8;
    const int n0 = row0, n1 = row1;
    const int jA  = j0 + 2 * tq;
    const int k2g = (j0 >> 1) + tq;
    const int wkt = k2g >> 3;
    const int wpp = k2g & 7;
    const int wtq = wpp & 3;
    const int wsl = (wpp >> 2) * 2;

    // bias registers (khalf0 gate threads)
    float2 bz = make_float2(0.f, 0.f), br2 = bz, bg2 = bz;
    float2 hp0 = make_float2(0.f, 0.f), hp1 = make_float2(0.f, 0.f);
    if (khalf == 0) {
        bz  = *reinterpret_cast<const float2*>(&bias[jA]);
        br2 = *reinterpret_cast<const float2*>(&bias[HH + jA]);
        bg2 = *reinterpret_cast<const float2*>(&bias[2 * HH + jA]);
    }

    const int ktb = khalf * 16;                  // base kt within each region

    for (int s = 0; s < TT; s++) {
        const int p   = s & 1;
        const int t_s = dir ? (TT - 1 - s) : s;
        const unsigned* __restrict__ xr0 = xbf + ((size_t)n0 * TT + t_s) * 512;
        const unsigned* __restrict__ xr1 = xbf + ((size_t)n1 * TT + t_s) * 512;
        const unsigned* __restrict__ hb  = hbf + ((size_t)dir * 2 + p)       * HB_PP;
        unsigned*       __restrict__ hbn = hbf + ((size_t)dir * 2 + (p ^ 1)) * HB_PP;

        // acc: 0 = z (x+h), 1 = r (x+h), 2 = gx, 3 = gh
        float acc[4][4];
#pragma unroll
        for (int nt = 0; nt < 4; nt++)
#pragma unroll
            for (int r = 0; r < 4; r++) acc[nt][r] = 0.f;

        // ================= x-part (independent of other blocks) ==============
        uint4 v0[2], v1[2];
        v0[0] = __ldg(reinterpret_cast<const uint4*>(&xr0[ktb * 16 + tq * 4]));
        v1[0] = __ldg(reinterpret_cast<const uint4*>(&xr1[ktb * 16 + tq * 4]));
#pragma unroll
        for (int ki = 0; ki < 16; ki++) {
            const int kt  = ktb + ki;
            const int cur = ki & 1;
            if (ki < 15) {
                v0[cur ^ 1] = __ldg(reinterpret_cast<const uint4*>(
                    &xr0[(kt + 1) * 16 + tq * 4]));
                v1[cur ^ 1] = __ldg(reinterpret_cast<const uint4*>(
                    &xr1[(kt + 1) * 16 + tq * 4]));
            }
            unsigned aH[4], aL[4];
            aH[0] = v0[cur].x; aH[1] = v1[cur].x; aH[2] = v0[cur].z; aH[3] = v1[cur].z;
            aL[0] = v0[cur].y; aL[1] = v1[cur].y; aL[2] = v0[cur].w; aL[3] = v1[cur].w;
#pragma unroll
            for (int nt = 0; nt < 3; nt++) {
                const uint4 bb = *reinterpret_cast<const uint4*>(
                    &bfr[((kt * 3 + nt) * 32 + l) * 4]);
                float* a = (nt == 2) ? acc[2] : acc[nt];
                mma_bf16(a, aH, bb.x, bb.y);
                mma_bf16(a, aL, bb.x, bb.y);
                mma_bf16(a, aH, bb.z, bb.w);
            }
        }

        // ================= barrier wait (h of step s-1 ready) ================
        if (t == 0 && s > 0) {
            const unsigned target = 64u * (unsigned)s;
            unsigned cur;
            do {
                asm volatile("ld.acquire.gpu.u32 %0, [%1];"
                             : "=r"(cur) : "l"(&g_arrive[dir]) : "memory");
            } while (cur < target);
        }
        __syncthreads();

        // ================= h-part ===========================================
        v0[0] = __ldg(reinterpret_cast<const uint4*>(&hb[n0 * 512 + ktb * 16 + tq * 4]));
        v1[0] = __ldg(reinterpret_cast<const uint4*>(&hb[n1 * 512 + ktb * 16 + tq * 4]));
#pragma unroll
        for (int ki = 0; ki < 16; ki++) {
            const int kth = ktb + ki;            // h-local kt
            const int kt  = 32 + kth;            // bfr index
            const int cur = ki & 1;
            if (ki < 15) {
                v0[cur ^ 1] = __ldg(reinterpret_cast<const uint4*>(
                    &hb[n0 * 512 + (kth + 1) * 16 + tq * 4]));
                v1[cur ^ 1] = __ldg(reinterpret_cast<const uint4*>(
                    &hb[n1 * 512 + (kth + 1) * 16 + tq * 4]));
            }
            unsigned aH[4], aL[4];
            aH[0] = v0[cur].x; aH[1] = v1[cur].x; aH[2] = v0[cur].z; aH[3] = v1[cur].z;
            aL[0] = v0[cur].y; aL[1] = v1[cur].y; aL[2] = v0[cur].w; aL[3] = v1[cur].w;
#pragma unroll
            for (int nt = 0; nt < 3; nt++) {
                const uint4 bb = *reinterpret_cast<const uint4*>(
                    &bfr[((kt * 3 + nt) * 32 + l) * 4]);
                float* a = (nt == 2) ? acc[3] : acc[nt];
                mma_bf16(a, aH, bb.x, bb.y);
                mma_bf16(a, aL, bb.x, bb.y);
                mma_bf16(a, aH, bb.z, bb.w);
            }
        }

        // ================= split-K exchange ==================================
        if (khalf == 1) {
#pragma unroll
            for (int nt = 0; nt < 4; nt++) {
                float4 v = make_float4(acc[nt][0], acc[nt][1], acc[nt][2], acc[nt][3]);
                *reinterpret_cast<float4*>(&red[((mt * 4 + nt) * 32 + l) * 4]) = v;
            }
        }
        __syncthreads();

        if (khalf == 0) {
#pragma unroll
            for (int nt = 0; nt < 4; nt++) {
                const float4 v = *reinterpret_cast<const float4*>(
                    &red[((mt * 4 + nt) * 32 + l) * 4]);
                acc[nt][0] += v.x; acc[nt][1] += v.y;
                acc[nt][2] += v.z; acc[nt][3] += v.w;
            }
            // gates: q0=(n0,jA) q1=(n0,jA+1) q2=(n1,jA) q3=(n1,jA+1)
            const float z0a = 1.f / (1.f + __expf(-(acc[0][0] + bz.x)));
            const float z0b = 1.f / (1.f + __expf(-(acc[0][1] + bz.y)));
            const float z1a = 1.f / (1.f + __expf(-(acc[0][2] + bz.x)));
            const float z1b = 1.f / (1.f + __expf(-(acc[0][3] + bz.y)));
            const float r0a = 1.f / (1.f + __expf(-(acc[1][0] + br2.x)));
            const float r0b = 1.f / (1.f + __expf(-(acc[1][1] + br2.y)));
            const float r1a = 1.f / (1.f + __expf(-(acc[1][2] + br2.x)));
            const float r1b = 1.f / (1.f + __expf(-(acc[1][3] + br2.y)));
            const float g0a = tanhf(acc[2][0] + bg2.x + r0a * acc[3][0]);
            const float g0b = tanhf(acc[2][1] + bg2.y + r0b * acc[3][1]);
            const float g1a = tanhf(acc[2][2] + bg2.x + r1a * acc[3][2]);
            const float g1b = tanhf(acc[2][3] + bg2.y + r1b * acc[3][3]);
            const float h0a = (1.f - z0a) * g0a + z0a * hp0.x;
            const float h0b = (1.f - z0b) * g0b + z0b * hp0.y;
            const float h1a = (1.f - z1a) * g1a + z1a * hp1.x;
            const float h1b = (1.f - z1b) * g1b + z1b * hp1.y;
            hp0 = make_float2(h0a, h0b);
            hp1 = make_float2(h1a, h1b);

            const int t_out = dir ? (TT - 1 - s) : s;
            *reinterpret_cast<float2*>(
                &out[((size_t)n0 * TT + t_out) * (2 * HH) + dir * HH + jA]) =
                make_float2(h0a, h0b);
            *reinterpret_cast<float2*>(
                &out[((size_t)n1 * TT + t_out) * (2 * HH) + dir * HH + jA]) =
                make_float2(h1a, h1b);
            *reinterpret_cast<uint2*>(&hbn[n0 * 512 + wkt * 16 + wtq * 4 + wsl]) =
                make_uint2(packbf(h0b, h0a), packbf(bfres(h0b), bfres(h0a)));
            *reinterpret_cast<uint2*>(&hbn[n1 * 512 + wkt * 16 + wtq * 4 + wsl]) =
                make_uint2(packbf(h1b, h1a), packbf(bfres(h1b), bfres(h1a)));
        }

        // ================= arrive (release) ==================================
        __syncthreads();
        if (t == 0) {
            unsigned old;
            asm volatile("atom.add.release.gpu.u32 %0, [%1], 1;"
                         : "=r"(old) : "l"(&g_arrive[dir]) : "memory");
        }
    }
}

// -----------------------------------------------------------------------------
// Launch
// -----------------------------------------------------------------------------
extern "C" void kernel_launch(void* const* d_in, const int* in_sizes, int n_in,
                              void* d_out, int out_size)
{
    (void)in_sizes; (void)n_in; (void)out_size;
    const float* x   = (const float*)d_in[0];
    const float* Wxf = (const float*)d_in[1];
    const float* Whf = (const float*)d_in[2];
    const float* bf  = (const float*)d_in[3];
    const float* Wxb = (const float*)d_in[4];
    const float* Whb = (const float*)d_in[5];
    const float* bb  = (const float*)d_in[6];
    float* out = (float*)d_out;

    unsigned *xbf, *hbf;
    cudaGetSymbolAddress((void**)&xbf, g_xbf);
    cudaGetSymbolAddress((void**)&hbf, g_hbf);

    cudaFuncSetAttribute(gru_fused_kernel,
                         cudaFuncAttributeMaxDynamicSharedMemorySize,
                         PMMA_SMEM);

    // 1) h bf16 buffers = 0, barrier counters = 0
    init_kernel<<<128, 256>>>(hbf);

    // 2) x -> fragment-ready bf16 hi/lo
    convert_x_kernel<<<4096, 256>>>(x, xbf);

    // 3) fused persistent BiGRU (projection + recurrence in one kernel)
    gru_fused_kernel<<<dim3(64, 2), 256, PMMA_SMEM>>>(
        Wxf, Whf, bf, Wxb, Whb, bb, xbf, hbf, out);
}

// round 10
// speedup vs baseline: 1.1949x; 1.1949x over previous
#include <cuda_runtime.h>
#include <cuda_bf16.h>
#include <cstdint>

// Problem constants
#define NB   64      // batch
#define TT   512     // time steps
#define DD   512     // input dim
#define HH   512     // hidden dim
#define G3   1536    // 3*H

// Scratch (device globals: allocation-free)
__device__ float    g_xm[(size_t)2 * NB * TT * G3];   // [dir][n][t][3H]
// bf16 h, fragment-ready layout: [dir][par][row(64)][kt(32)][tq(4)][4]
__device__ unsigned g_hbf[2 * 2 * 64 * 512];
__device__ unsigned g_arrive[2];                      // monotonic barrier counters

__device__ __forceinline__ unsigned packbf(float odd_k, float even_k) {
    unsigned r;
    asm("cvt.rn.bf16x2.f32 %0, %1, %2;" : "=r"(r) : "f"(odd_k), "f"(even_k));
    return r;
}
__device__ __forceinline__ float bfres(float x) {
    return x - __bfloat162float(__float2bfloat16_rn(x));
}
__device__ __forceinline__ void mma_bf16(float* c, const unsigned* a,
                                         unsigned b0, unsigned b1) {
    asm volatile(
        "mma.sync.aligned.m16n8k16.row.col.f32.bf16.bf16.f32 "
        "{%0,%1,%2,%3}, {%4,%5,%6,%7}, {%8,%9}, {%0,%1,%2,%3};"
        : "+f"(c[0]), "+f"(c[1]), "+f"(c[2]), "+f"(c[3])
        : "r"(a[0]), "r"(a[1]), "r"(a[2]), "r"(a[3]), "r"(b0), "r"(b1));
}
__device__ __forceinline__ void ldsm_x4(unsigned& r0, unsigned& r1,
                                        unsigned& r2, unsigned& r3, unsigned sa) {
    asm volatile("ldmatrix.sync.aligned.m8n8.x4.shared.b16 {%0,%1,%2,%3}, [%4];"
                 : "=r"(r0), "=r"(r1), "=r"(r2), "=r"(r3) : "r"(sa));
}
__device__ __forceinline__ unsigned sm32(const void* p) {
    return (unsigned)__cvta_generic_to_shared(p);
}

// -----------------------------------------------------------------------------
// Init: zero bf16 h buffers + barrier counters
// -----------------------------------------------------------------------------
__global__ void init_kernel(unsigned* hbf) {
    int i = blockIdx.x * blockDim.x + threadIdx.x;   // 32768 uint4s
    reinterpret_cast<uint4*>(hbf)[i] = make_uint4(0u, 0u, 0u, 0u);
    if (i == 0) { g_arrive[0] = 0; g_arrive[1] = 0; }
}

// -----------------------------------------------------------------------------
// Input projection GEMM: bf16 MMA, 3-pass hi/lo split, ldmatrix fragment loads.
// (identical to R8 — proven at 3730us total)
// -----------------------------------------------------------------------------
#define ARS 12

__global__ __launch_bounds__(256, 2) void sgemm_xm_bf16x3_kernel(
    const float* __restrict__ x,
    const float* __restrict__ Wx_f, const float* __restrict__ Wx_b,
    const float* __restrict__ b_f,  const float* __restrict__ b_b,
    float* __restrict__ xm)
{
    const int dir = blockIdx.z;
    const float* __restrict__ Wx   = dir ? Wx_b : Wx_f;
    const float* __restrict__ bias = dir ? b_b  : b_f;
    float* __restrict__ C = xm + (size_t)dir * (NB * TT) * G3;

    __shared__ __align__(16) unsigned AH[128 * ARS];
    __shared__ __align__(16) unsigned AL[128 * ARS];
    __shared__ __align__(16) unsigned BH[128 * ARS];
    __shared__ __align__(16) unsigned BL[128 * ARS];

    const int t = threadIdx.x;
    const int w = t >> 5;
    const int l = t & 31;
    const int warp_m = w >> 1;
    const int warp_n = w & 1;
    const int gid = l >> 2;
    const int tig = l & 3;

    const int mBase = blockIdx.y * 128;
    const int jBase = blockIdx.x * 128;

    const int aM  = t & 127;
    const int aKg = (t >> 7) * 8;
    const int am  = mBase + aM;
    const int an  = am >> 9;
    const int at0 = am & 511;
    const int ats = dir ? (TT - 1 - at0) : at0;
    const float* __restrict__ aPtr = x + ((size_t)an * TT + ats) * DD + aKg;
    const int aCol = aKg >> 1;

    const int bKp = t & 7;
    const int bN  = (t >> 3) * 4;
    const float* __restrict__ bPtr = Wx + (size_t)(2 * bKp) * G3 + jBase + bN;

    unsigned aAdH[2], aAdL[2], bAdH[4], bAdL[4];
    {
        const int rowA = warp_m * 32 + (l & 7) + 8 * ((l >> 3) & 1);
        const int chA  = l >> 4;
#pragma unroll
        for (int mt = 0; mt < 2; mt++) {
            const int r = rowA + mt * 16;
            aAdH[mt] = sm32(&AH[r * ARS + chA * 4]);
            aAdL[mt] = sm32(&AL[r * ARS + chA * 4]);
        }
        const int rowB = warp_n * 64 + (l & 7) + 8 * ((l >> 4) & 1);
        const int chB  = (l >> 3) & 1;
#pragma unroll
        for (int np = 0; np < 4; np++) {
            const int n = rowB + np * 16;
            bAdH[np] = sm32(&BH[n * ARS + chB * 4]);
            bAdL[np] = sm32(&BL[n * ARS + chB * 4]);
        }
    }

    float acc[2][8][4];
#pragma unroll
    for (int mt = 0; mt < 2; mt++)
#pragma unroll
        for (int nt = 0; nt < 8; nt++)
#pragma unroll
            for (int r = 0; r < 4; r++) acc[mt][nt][r] = 0.f;

    float4 av0 = *reinterpret_cast<const float4*>(aPtr);
    float4 av1 = *reinterpret_cast<const float4*>(aPtr + 4);
    float4 be  = *reinterpret_cast<const float4*>(bPtr);
    float4 bo  = *reinterpret_cast<const float4*>(bPtr + G3);

    for (int k0 = 0; k0 < DD; k0 += 16) {
        {
            uint4 hh, ll;
            hh.x = packbf(av0.y, av0.x); hh.y = packbf(av0.w, av0.z);
            hh.z = packbf(av1.y, av1.x); hh.w = packbf(av1.w, av1.z);
            ll.x = packbf(bfres(av0.y), bfres(av0.x));
            ll.y = packbf(bfres(av0.w), bfres(av0.z));
            ll.z = packbf(bfres(av1.y), bfres(av1.x));
            ll.w = packbf(bfres(av1.w), bfres(av1.z));
            *reinterpret_cast<uint4*>(&AH[aM * ARS + aCol]) = hh;
            *reinterpret_cast<uint4*>(&AL[aM * ARS + aCol]) = ll;
        }
        {
            const float ee[4] = {be.x, be.y, be.z, be.w};
            const float oo[4] = {bo.x, bo.y, bo.z, bo.w};
#pragma unroll
            for (int c = 0; c < 4; c++) {
                BH[(bN + c) * ARS + bKp] = packbf(oo[c], ee[c]);
                BL[(bN + c) * ARS + bKp] = packbf(bfres(oo[c]), bfres(ee[c]));
            }
        }
        __syncthreads();

        if (k0 + 16 < DD) {
            av0 = *reinterpret_cast<const float4*>(aPtr + k0 + 16);
            av1 = *reinterpret_cast<const float4*>(aPtr + k0 + 20);
            be  = *reinterpret_cast<const float4*>(bPtr + (size_t)(k0 + 16) * G3);
            bo  = *reinterpret_cast<const float4*>(bPtr + (size_t)(k0 + 16) * G3 + G3);
        }

        unsigned ahi[2][4], alo[2][4];
#pragma unroll
        for (int mt = 0; mt < 2; mt++) {
            ldsm_x4(ahi[mt][0], ahi[mt][1], ahi[mt][2], ahi[mt][3], aAdH[mt]);
            ldsm_x4(alo[mt][0], alo[mt][1], alo[mt][2], alo[mt][3], aAdL[mt]);
        }
#pragma unroll
        for (int np = 0; np < 4; np++) {
            unsigned bh[4], bl[4];
            ldsm_x4(bh[0], bh[1], bh[2], bh[3], bAdH[np]);
            ldsm_x4(bl[0], bl[1], bl[2], bl[3], bAdL[np]);
#pragma unroll
            for (int tile = 0; tile < 2; tile++) {
                const int nt = np * 2 + tile;
#pragma unroll
                for (int mt = 0; mt < 2; mt++) {
                    mma_bf16(acc[mt][nt], ahi[mt], bh[2 * tile], bh[2 * tile + 1]);
                    mma_bf16(acc[mt][nt], alo[mt], bh[2 * tile], bh[2 * tile + 1]);
                    mma_bf16(acc[mt][nt], ahi[mt], bl[2 * tile], bl[2 * tile + 1]);
                }
            }
        }
        __syncthreads();
    }

#pragma unroll
    for (int mt = 0; mt < 2; mt++) {
        const int m0 = mBase + warp_m * 32 + mt * 16 + gid;
        const int m1 = m0 + 8;
#pragma unroll
        for (int nt = 0; nt < 8; nt++) {
            const int col = jBase + warp_n * 64 + nt * 8 + tig * 2;
            const float2 bv = *reinterpret_cast<const float2*>(&bias[col]);
            float2 o0, o1;
            o0.x = acc[mt][nt][0] + bv.x;  o0.y = acc[mt][nt][1] + bv.y;
            o1.x = acc[mt][nt][2] + bv.x;  o1.y = acc[mt][nt][3] + bv.y;
            *reinterpret_cast<float2*>(&C[(size_t)m0 * G3 + col]) = o0;
            *reinterpret_cast<float2*>(&C[(size_t)m1 * G3 + col]) = o1;
        }
    }
}

// -----------------------------------------------------------------------------
// Persistent recurrence (tensor-core). vs R8:
//  - depth-4 LDG software pipeline in the h fragment loads (hides L2 latency
//    under the MMA stream; R8's depth-1 exposed ~100cyc/iter)
//  - hbn (cross-block dependency) stores issued before out/prefetch
// -----------------------------------------------------------------------------
#define BFRAG_UINTS  (32 * 3 * 32 * 4)           // 12288
#define REDF         (12 * 32 * 4)               // 1536 floats
#define PMMA_SMEM    ((BFRAG_UINTS + REDF) * 4)  // 55296 B
#define HB_PP        32768                       // uints per (dir,parity)

__global__ __launch_bounds__(256, 1) void gru_persist_mma_kernel(
    const float* __restrict__ Wh_f, const float* __restrict__ Wh_b,
    const float* __restrict__ xm, unsigned* __restrict__ hbf,
    float* __restrict__ out)
{
    extern __shared__ unsigned smu[];
    unsigned* bfr = smu;
    float* red = reinterpret_cast<float*>(smu + BFRAG_UINTS);

    const int dir = blockIdx.y;
    const int j0  = blockIdx.x * 8;
    const float* __restrict__ Wh = dir ? Wh_b : Wh_f;

    const int t  = threadIdx.x;
    const int w  = t >> 5;
    const int l  = t & 31;
    const int g  = l >> 2;
    const int tq = l & 3;
    const int mt = w & 3;
    const int khalf = w >> 2;

    // ---- fill W B-fragments once ----
    for (int idx = t; idx < 24 * 256; idx += 256) {
        const int c_loc = idx >> 8;
        const int k2    = idx & 255;
        const int gate  = c_loc >> 3;
        const int jj    = c_loc & 7;
        const int col   = gate * HH + j0 + jj;
        const float e = Wh[(size_t)(2 * k2) * G3 + col];
        const float o = Wh[(size_t)(2 * k2 + 1) * G3 + col];
        const int kt = k2 >> 3;
        const int pp = k2 & 7;
        const int rr = pp >> 2;
        const int ts = pp & 3;
        const int off4 = ((kt * 3 + gate) * 32 + jj * 4 + ts) * 4;
        bfr[off4 + rr]     = packbf(o, e);
        bfr[off4 + 2 + rr] = packbf(bfres(o), bfres(e));
    }
    __syncthreads();

    const int row0 = mt * 16 + g;
    const int row1 = row0 + 8;
    const int n0 = row0, n1 = row1;
    const int jA  = j0 + 2 * tq;
    const int k2g = (j0 >> 1) + tq;
    const int wkt = k2g >> 3;
    const int wpp = k2g & 7;
    const int wtq = wpp & 3;
    const int wsl = (wpp >> 2) * 2;
    const float* xmd = xm + (size_t)dir * (NB * TT) * G3;

    // persistent gate-input registers + register-resident h_prev
    float2 xz0, xr0, xg0, xz1, xr1, xg1;
    float2 hp0 = make_float2(0.f, 0.f), hp1 = make_float2(0.f, 0.f);
    if (khalf == 0) {
        const float* b0 = &xmd[((size_t)n0 * TT + 0) * G3 + jA];
        const float* b1 = &xmd[((size_t)n1 * TT + 0) * G3 + jA];
        xz0 = __ldg((const float2*)(b0));
        xr0 = __ldg((const float2*)(b0 + HH));
        xg0 = __ldg((const float2*)(b0 + 2 * HH));
        xz1 = __ldg((const float2*)(b1));
        xr1 = __ldg((const float2*)(b1 + HH));
        xg1 = __ldg((const float2*)(b1 + 2 * HH));
    }

    const int ktb = khalf * 16;

    for (int s = 0; s < TT; s++) {
        const int p = s & 1;
        const unsigned* __restrict__ hb  = hbf + ((size_t)dir * 2 + p)       * HB_PP;
        unsigned*       __restrict__ hbn = hbf + ((size_t)dir * 2 + (p ^ 1)) * HB_PP;

        // ---- MMA mainloop, depth-4 LDG pipeline ----
        float acc[3][4];
#pragma unroll
        for (int nt = 0; nt < 3; nt++)
#pragma unroll
            for (int r = 0; r < 4; r++) acc[nt][r] = 0.f;

        uint4 v0[4], v1[4];
#pragma unroll
        for (int pf = 0; pf < 4; pf++) {
            v0[pf] = __ldg(reinterpret_cast<const uint4*>(
                &hb[row0 * 512 + (ktb + pf) * 16 + tq * 4]));
            v1[pf] = __ldg(reinterpret_cast<const uint4*>(
                &hb[row1 * 512 + (ktb + pf) * 16 + tq * 4]));
        }
#pragma unroll
        for (int ki = 0; ki < 16; ki++) {
            const int kt  = ktb + ki;
            const int cur = ki & 3;
            // consume buffer into fragment regs BEFORE refilling it
            unsigned aH[4], aL[4];
            aH[0] = v0[cur].x; aH[1] = v1[cur].x; aH[2] = v0[cur].z; aH[3] = v1[cur].z;
            aL[0] = v0[cur].y; aL[1] = v1[cur].y; aL[2] = v0[cur].w; aL[3] = v1[cur].w;
            if (ki < 12) {
                v0[cur] = __ldg(reinterpret_cast<const uint4*>(
                    &hb[row0 * 512 + (kt + 4) * 16 + tq * 4]));
                v1[cur] = __ldg(reinterpret_cast<const uint4*>(
                    &hb[row1 * 512 + (kt + 4) * 16 + tq * 4]));
            }
#pragma unroll
            for (int nt = 0; nt < 3; nt++) {
                const uint4 bb = *reinterpret_cast<const uint4*>(
                    &bfr[((kt * 3 + nt) * 32 + l) * 4]);
                mma_bf16(acc[nt], aH, bb.x, bb.y);
                mma_bf16(acc[nt], aL, bb.x, bb.y);
                mma_bf16(acc[nt], aH, bb.z, bb.w);
            }
        }

        // ---- split-K exchange ----
        if (khalf == 1) {
#pragma unroll
            for (int nt = 0; nt < 3; nt++) {
                float4 v = make_float4(acc[nt][0], acc[nt][1], acc[nt][2], acc[nt][3]);
                *reinterpret_cast<float4*>(&red[((mt * 3 + nt) * 32 + l) * 4]) = v;
            }
        }
        __syncthreads();

        if (khalf == 0) {
#pragma unroll
            for (int nt = 0; nt < 3; nt++) {
                const float4 v = *reinterpret_cast<const float4*>(
                    &red[((mt * 3 + nt) * 32 + l) * 4]);
                acc[nt][0] += v.x; acc[nt][1] += v.y;
                acc[nt][2] += v.z; acc[nt][3] += v.w;
            }
            const float z0a = 1.f / (1.f + __expf(-(xz0.x + acc[0][0])));
            const float z0b = 1.f / (1.f + __expf(-(xz0.y + acc[0][1])));
            const float z1a = 1.f / (1.f + __expf(-(xz1.x + acc[0][2])));
            const float z1b = 1.f / (1.f + __expf(-(xz1.y + acc[0][3])));
            const float r0a = 1.f / (1.f + __expf(-(xr0.x + acc[1][0])));
            const float r0b = 1.f / (1.f + __expf(-(xr0.y + acc[1][1])));
            const float r1a = 1.f / (1.f + __expf(-(xr1.x + acc[1][2])));
            const float r1b = 1.f / (1.f + __expf(-(xr1.y + acc[1][3])));
            const float g0a = tanhf(xg0.x + r0a * acc[2][0]);
            const float g0b = tanhf(xg0.y + r0b * acc[2][1]);
            const float g1a = tanhf(xg1.x + r1a * acc[2][2]);
            const float g1b = tanhf(xg1.y + r1b * acc[2][3]);
            const float h0a = (1.f - z0a) * g0a + z0a * hp0.x;
            const float h0b = (1.f - z0b) * g0b + z0b * hp0.y;
            const float h1a = (1.f - z1a) * g1a + z1a * hp1.x;
            const float h1b = (1.f - z1b) * g1b + z1b * hp1.y;
            hp0 = make_float2(h0a, h0b);
            hp1 = make_float2(h1a, h1b);

            // cross-block dependency stores FIRST
            *reinterpret_cast<uint2*>(&hbn[n0 * 512 + wkt * 16 + wtq * 4 + wsl]) =
                make_uint2(packbf(h0b, h0a), packbf(bfres(h0b), bfres(h0a)));
            *reinterpret_cast<uint2*>(&hbn[n1 * 512 + wkt * 16 + wtq * 4 + wsl]) =
                make_uint2(packbf(h1b, h1a), packbf(bfres(h1b), bfres(h1a)));

            const int t_out = dir ? (TT - 1 - s) : s;
            *reinterpret_cast<float2*>(
                &out[((size_t)n0 * TT + t_out) * (2 * HH) + dir * HH + jA]) =
                make_float2(h0a, h0b);
            *reinterpret_cast<float2*>(
                &out[((size_t)n1 * TT + t_out) * (2 * HH) + dir * HH + jA]) =
                make_float2(h1a, h1b);

            // prefetch next step's gate inputs (before the barrier)
            if (s + 1 < TT) {
                const float* b0 = &xmd[((size_t)n0 * TT + (s + 1)) * G3 + jA];
                const float* b1 = &xmd[((size_t)n1 * TT + (s + 1)) * G3 + jA];
                xz0 = __ldg((const float2*)(b0));
                xr0 = __ldg((const float2*)(b0 + HH));
                xg0 = __ldg((const float2*)(b0 + 2 * HH));
                xz1 = __ldg((const float2*)(b1));
                xr1 = __ldg((const float2*)(b1 + HH));
                xg1 = __ldg((const float2*)(b1 + 2 * HH));
            }
        }

        // ---- per-direction release/acquire barrier (monotonic counter) ----
        __syncthreads();
        if (t == 0) {
            unsigned old;
            asm volatile("atom.add.release.gpu.u32 %0, [%1], 1;"
                         : "=r"(old) : "l"(&g_arrive[dir]) : "memory");
            const unsigned target = 64u * (unsigned)(s + 1);
            unsigned cur;
            do {
                asm volatile("ld.acquire.gpu.u32 %0, [%1];"
                             : "=r"(cur) : "l"(&g_arrive[dir]) : "memory");
            } while (cur < target);
        }
        __syncthreads();
    }
}

// -----------------------------------------------------------------------------
// Launch
// -----------------------------------------------------------------------------
extern "C" void kernel_launch(void* const* d_in, const int* in_sizes, int n_in,
                              void* d_out, int out_size)
{
    (void)in_sizes; (void)n_in; (void)out_size;
    const float* x   = (const float*)d_in[0];
    const float* Wxf = (const float*)d_in[1];
    const float* Whf = (const float*)d_in[2];
    const float* bf  = (const float*)d_in[3];
    const float* Wxb = (const float*)d_in[4];
    const float* Whb = (const float*)d_in[5];
    const float* bb  = (const float*)d_in[6];
    float* out = (float*)d_out;

    float* xm;
    unsigned* hbf;
    cudaGetSymbolAddress((void**)&xm, g_xm);
    cudaGetSymbolAddress((void**)&hbf, g_hbf);

    cudaFuncSetAttribute(gru_persist_mma_kernel,
                         cudaFuncAttributeMaxDynamicSharedMemorySize,
                         PMMA_SMEM);

    // 1) h bf16 buffers = 0, barrier counters = 0
    init_kernel<<<128, 256>>>(hbf);

    // 2) input projections: bf16 MMA + ldmatrix, pipelined
    sgemm_xm_bf16x3_kernel<<<dim3(12, 256, 2), 256>>>(x, Wxf, Wxb, bf, bb, xm);

    // 3) persistent recurrence (depth-4 pipelined h loads)
    gru_persist_mma_kernel<<<dim3(64, 2), 256, PMMA_SMEM>>>(
        Whf, Whb, xm, hbf, out);
}

// round 12
// speedup vs baseline: 1.3089x; 1.0954x over previous
#include <cuda_runtime.h>
#include <cuda_bf16.h>
#include <cuda_fp16.h>
#include <cstdint>

// Problem constants
#define NB   64      // batch
#define TT   512     // time steps
#define DD   512     // input dim
#define HH   512     // hidden dim
#define G3   1536    // 3*H

// Scratch (device globals: allocation-free)
__device__ float    g_xm[(size_t)2 * NB * TT * G3];   // [dir][n][t][3H]
// fp16 h, fragment-ready layout: [dir][par][row(64)][kt(32)][tq(4)][4]
//   cell = { hi(k2), lo(k2), hi(k2+4), lo(k2+4) }  (fp16x2 each)
__device__ unsigned g_hbf[2 * 2 * 64 * 512];
__device__ unsigned g_arrive[2];                      // monotonic barrier counters

// ---- fp16 packing helpers (A-side hi/lo split; W is single fp16) ----
__device__ __forceinline__ unsigned packh(float odd_k, float even_k) {
    unsigned r;
    asm("cvt.rn.f16x2.f32 %0, %1, %2;" : "=r"(r) : "f"(odd_k), "f"(even_k));
    return r;
}
__device__ __forceinline__ float hres(float x) {
    return x - __half2float(__float2half_rn(x));
}
__device__ __forceinline__ void mma_f16(float* c, const unsigned* a,
                                        unsigned b0, unsigned b1) {
    asm volatile(
        "mma.sync.aligned.m16n8k16.row.col.f32.f16.f16.f32 "
        "{%0,%1,%2,%3}, {%4,%5,%6,%7}, {%8,%9}, {%0,%1,%2,%3};"
        : "+f"(c[0]), "+f"(c[1]), "+f"(c[2]), "+f"(c[3])
        : "r"(a[0]), "r"(a[1]), "r"(a[2]), "r"(a[3]), "r"(b0), "r"(b1));
}
__device__ __forceinline__ void ldsm_x4(unsigned& r0, unsigned& r1,
                                        unsigned& r2, unsigned& r3, unsigned sa) {
    asm volatile("ldmatrix.sync.aligned.m8n8.x4.shared.b16 {%0,%1,%2,%3}, [%4];"
                 : "=r"(r0), "=r"(r1), "=r"(r2), "=r"(r3) : "r"(sa));
}
__device__ __forceinline__ unsigned sm32(const void* p) {
    return (unsigned)__cvta_generic_to_shared(p);
}

// -----------------------------------------------------------------------------
// Init: zero fp16 h buffers + barrier counters
// -----------------------------------------------------------------------------
__global__ void init_kernel(unsigned* hbf) {
    int i = blockIdx.x * blockDim.x + threadIdx.x;   // 32768 uint4s
    reinterpret_cast<uint4*>(hbf)[i] = make_uint4(0u, 0u, 0u, 0u);
    if (i == 0) { g_arrive[0] = 0; g_arrive[1] = 0; }
}

// -----------------------------------------------------------------------------
// Input projection GEMM: fp16 MMA, 2-pass A-side hi/lo split, ldmatrix loads.
//   xm = (x_hi + x_lo) @ W_fp16 + bias      (error ~ x * w_lo ~ 2^-11)
// SMEM tiles: row-major k-consecutive fp16x2, row stride 12 uints (LDSM
// conflict-free). Per warp per k-tile: 8 LDSM.x4 + 32 MMA. Register-prefetch
// pipeline. Grid: (12, 256, 2).
// -----------------------------------------------------------------------------
#define ARS 12

__global__ __launch_bounds__(256, 2) void sgemm_xm_f16_kernel(
    const float* __restrict__ x,
    const float* __restrict__ Wx_f, const float* __restrict__ Wx_b,
    const float* __restrict__ b_f,  const float* __restrict__ b_b,
    float* __restrict__ xm)
{
    const int dir = blockIdx.z;
    const float* __restrict__ Wx   = dir ? Wx_b : Wx_f;
    const float* __restrict__ bias = dir ? b_b  : b_f;
    float* __restrict__ C = xm + (size_t)dir * (NB * TT) * G3;

    __shared__ __align__(16) unsigned AH[128 * ARS];
    __shared__ __align__(16) unsigned AL[128 * ARS];
    __shared__ __align__(16) unsigned BH[128 * ARS];

    const int t = threadIdx.x;
    const int w = t >> 5;
    const int l = t & 31;
    const int warp_m = w >> 1;
    const int warp_n = w & 1;
    const int gid = l >> 2;
    const int tig = l & 3;

    const int mBase = blockIdx.y * 128;
    const int jBase = blockIdx.x * 128;

    const int aM  = t & 127;
    const int aKg = (t >> 7) * 8;
    const int am  = mBase + aM;
    const int an  = am >> 9;
    const int at0 = am & 511;
    const int ats = dir ? (TT - 1 - at0) : at0;
    const float* __restrict__ aPtr = x + ((size_t)an * TT + ats) * DD + aKg;
    const int aCol = aKg >> 1;

    const int bKp = t & 7;
    const int bN  = (t >> 3) * 4;
    const float* __restrict__ bPtr = Wx + (size_t)(2 * bKp) * G3 + jBase + bN;

    unsigned aAdH[2], aAdL[2], bAdH[4];
    {
        const int rowA = warp_m * 32 + (l & 7) + 8 * ((l >> 3) & 1);
        const int chA  = l >> 4;
#pragma unroll
        for (int mt = 0; mt < 2; mt++) {
            const int r = rowA + mt * 16;
            aAdH[mt] = sm32(&AH[r * ARS + chA * 4]);
            aAdL[mt] = sm32(&AL[r * ARS + chA * 4]);
        }
        const int rowB = warp_n * 64 + (l & 7) + 8 * ((l >> 4) & 1);
        const int chB  = (l >> 3) & 1;
#pragma unroll
        for (int np = 0; np < 4; np++) {
            const int n = rowB + np * 16;
            bAdH[np] = sm32(&BH[n * ARS + chB * 4]);
        }
    }

    float acc[2][8][4];
#pragma unroll
    for (int mt = 0; mt < 2; mt++)
#pragma unroll
        for (int nt = 0; nt < 8; nt++)
#pragma unroll
            for (int r = 0; r < 4; r++) acc[mt][nt][r] = 0.f;

    float4 av0 = *reinterpret_cast<const float4*>(aPtr);
    float4 av1 = *reinterpret_cast<const float4*>(aPtr + 4);
    float4 be  = *reinterpret_cast<const float4*>(bPtr);
    float4 bo  = *reinterpret_cast<const float4*>(bPtr + G3);

    for (int k0 = 0; k0 < DD; k0 += 16) {
        {
            uint4 hh, ll;
            hh.x = packh(av0.y, av0.x); hh.y = packh(av0.w, av0.z);
            hh.z = packh(av1.y, av1.x); hh.w = packh(av1.w, av1.z);
            ll.x = packh(hres(av0.y), hres(av0.x));
            ll.y = packh(hres(av0.w), hres(av0.z));
            ll.z = packh(hres(av1.y), hres(av1.x));
            ll.w = packh(hres(av1.w), hres(av1.z));
            *reinterpret_cast<uint4*>(&AH[aM * ARS + aCol]) = hh;
            *reinterpret_cast<uint4*>(&AL[aM * ARS + aCol]) = ll;
        }
        {
            const float ee[4] = {be.x, be.y, be.z, be.w};
            const float oo[4] = {bo.x, bo.y, bo.z, bo.w};
#pragma unroll
            for (int c = 0; c < 4; c++)
                BH[(bN + c) * ARS + bKp] = packh(oo[c], ee[c]);
        }
        __syncthreads();

        if (k0 + 16 < DD) {
            av0 = *reinterpret_cast<const float4*>(aPtr + k0 + 16);
            av1 = *reinterpret_cast<const float4*>(aPtr + k0 + 20);
            be  = *reinterpret_cast<const float4*>(bPtr + (size_t)(k0 + 16) * G3);
            bo  = *reinterpret_cast<const float4*>(bPtr + (size_t)(k0 + 16) * G3 + G3);
        }

        unsigned ahi[2][4], alo[2][4];
#pragma unroll
        for (int mt = 0; mt < 2; mt++) {
            ldsm_x4(ahi[mt][0], ahi[mt][1], ahi[mt][2], ahi[mt][3], aAdH[mt]);
            ldsm_x4(alo[mt][0], alo[mt][1], alo[mt][2], alo[mt][3], aAdL[mt]);
        }
#pragma unroll
        for (int np = 0; np < 4; np++) {
            unsigned bh[4];
            ldsm_x4(bh[0], bh[1], bh[2], bh[3], bAdH[np]);
#pragma unroll
            for (int tile = 0; tile < 2; tile++) {
                const int nt = np * 2 + tile;
#pragma unroll
                for (int mt = 0; mt < 2; mt++) {
                    mma_f16(acc[mt][nt], ahi[mt], bh[2 * tile], bh[2 * tile + 1]);
                    mma_f16(acc[mt][nt], alo[mt], bh[2 * tile], bh[2 * tile + 1]);
                }
            }
        }
        __syncthreads();
    }

#pragma unroll
    for (int mt = 0; mt < 2; mt++) {
        const int m0 = mBase + warp_m * 32 + mt * 16 + gid;
        const int m1 = m0 + 8;
#pragma unroll
        for (int nt = 0; nt < 8; nt++) {
            const int col = jBase + warp_n * 64 + nt * 8 + tig * 2;
            const float2 bv = *reinterpret_cast<const float2*>(&bias[col]);
            float2 o0, o1;
            o0.x = acc[mt][nt][0] + bv.x;  o0.y = acc[mt][nt][1] + bv.y;
            o1.x = acc[mt][nt][2] + bv.x;  o1.y = acc[mt][nt][3] + bv.y;
            *reinterpret_cast<float2*>(&C[(size_t)m0 * G3 + col]) = o0;
            *reinterpret_cast<float2*>(&C[(size_t)m1 * G3 + col]) = o1;
        }
    }
}

// -----------------------------------------------------------------------------
// Persistent recurrence: fp16 2-pass (A-side split), structure = proven R10.
// Per ki: 2 LDG.128 (h hi+lo) + 3 LDS.64 (W) + 6 MMA.
// -----------------------------------------------------------------------------
#define BFRAG_UINTS  (32 * 3 * 32 * 2)           // 6144 -> 24KB
#define REDF         (12 * 32 * 4)               // 1536 floats
#define PMMA_SMEM    ((BFRAG_UINTS + REDF) * 4)  // 30720 B
#define HB_PP        32768                       // uints per (dir,parity)

__global__ __launch_bounds__(256, 1) void gru_persist_mma_kernel(
    const float* __restrict__ Wh_f, const float* __restrict__ Wh_b,
    const float* __restrict__ xm, unsigned* __restrict__ hbf,
    float* __restrict__ out)
{
    extern __shared__ unsigned smu[];
    unsigned* bfr = smu;                         // [kt][gate][lane][2] = bh0,bh1
    float* red = reinterpret_cast<float*>(smu + BFRAG_UINTS);

    const int dir = blockIdx.y;
    const int j0  = blockIdx.x * 8;
    const float* __restrict__ Wh = dir ? Wh_b : Wh_f;

    const int t  = threadIdx.x;
    const int w  = t >> 5;
    const int l  = t & 31;
    const int g  = l >> 2;
    const int tq = l & 3;
    const int mt = w & 3;
    const int khalf = w >> 2;

    // ---- fill W B-fragments once (fp16, no lo pass) ----
    for (int idx = t; idx < 24 * 256; idx += 256) {
        const int c_loc = idx >> 8;
        const int k2    = idx & 255;
        const int gate  = c_loc >> 3;
        const int jj    = c_loc & 7;
        const int col   = gate * HH + j0 + jj;
        const float e = Wh[(size_t)(2 * k2) * G3 + col];
        const float o = Wh[(size_t)(2 * k2 + 1) * G3 + col];
        const int kt = k2 >> 3;
        const int pp = k2 & 7;
        const int rr = pp >> 2;
        const int ts = pp & 3;
        const int off2 = ((kt * 3 + gate) * 32 + jj * 4 + ts) * 2;
        bfr[off2 + rr] = packh(o, e);
    }
    __syncthreads();

    const int row0 = mt * 16 + g;
    const int row1 = row0 + 8;
    const int n0 = row0, n1 = row1;
    const int jA  = j0 + 2 * tq;
    const int k2g = (j0 >> 1) + tq;
    const int wkt = k2g >> 3;
    const int wpp = k2g & 7;
    const int wtq = wpp & 3;
    const int wsl = (wpp >> 2) * 2;
    const float* xmd = xm + (size_t)dir * (NB * TT) * G3;

    float2 xz0, xr0, xg0, xz1, xr1, xg1;
    float2 hp0 = make_float2(0.f, 0.f), hp1 = make_float2(0.f, 0.f);
    if (khalf == 0) {
        const float* b0 = &xmd[((size_t)n0 * TT + 0) * G3 + jA];
        const float* b1 = &xmd[((size_t)n1 * TT + 0) * G3 + jA];
        xz0 = __ldg((const float2*)(b0));
        xr0 = __ldg((const float2*)(b0 + HH));
        xg0 = __ldg((const float2*)(b0 + 2 * HH));
        xz1 = __ldg((const float2*)(b1));
        xr1 = __ldg((const float2*)(b1 + HH));
        xg1 = __ldg((const float2*)(b1 + 2 * HH));
    }

    const int ktb = khalf * 16;

    for (int s = 0; s < TT; s++) {
        const int p = s & 1;
        const unsigned* __restrict__ hb  = hbf + ((size_t)dir * 2 + p)       * HB_PP;
        unsigned*       __restrict__ hbn = hbf + ((size_t)dir * 2 + (p ^ 1)) * HB_PP;

        float acc[3][4];
#pragma unroll
        for (int nt = 0; nt < 3; nt++)
#pragma unroll
            for (int r = 0; r < 4; r++) acc[nt][r] = 0.f;

        uint4 v0[4], v1[4];
#pragma unroll
        for (int pf = 0; pf < 4; pf++) {
            v0[pf] = __ldg(reinterpret_cast<const uint4*>(
                &hb[row0 * 512 + (ktb + pf) * 16 + tq * 4]));
            v1[pf] = __ldg(reinterpret_cast<const uint4*>(
                &hb[row1 * 512 + (ktb + pf) * 16 + tq * 4]));
        }
#pragma unroll
        for (int ki = 0; ki < 16; ki++) {
            const int kt  = ktb + ki;
            const int cur = ki & 3;
            unsigned aH[4], aL[4];
            aH[0] = v0[cur].x; aH[1] = v1[cur].x; aH[2] = v0[cur].z; aH[3] = v1[cur].z;
            aL[0] = v0[cur].y; aL[1] = v1[cur].y; aL[2] = v0[cur].w; aL[3] = v1[cur].w;
            if (ki < 12) {
                v0[cur] = __ldg(reinterpret_cast<const uint4*>(
                    &hb[row0 * 512 + (kt + 4) * 16 + tq * 4]));
                v1[cur] = __ldg(reinterpret_cast<const uint4*>(
                    &hb[row1 * 512 + (kt + 4) * 16 + tq * 4]));
            }
#pragma unroll
            for (int nt = 0; nt < 3; nt++) {
                const uint2 bb = *reinterpret_cast<const uint2*>(
                    &bfr[((kt * 3 + nt) * 32 + l) * 2]);
                mma_f16(acc[nt], aH, bb.x, bb.y);
                mma_f16(acc[nt], aL, bb.x, bb.y);
            }
        }

        if (khalf == 1) {
#pragma unroll
            for (int nt = 0; nt < 3; nt++) {
                float4 v = make_float4(acc[nt][0], acc[nt][1], acc[nt][2], acc[nt][3]);
                *reinterpret_cast<float4*>(&red[((mt * 3 + nt) * 32 + l) * 4]) = v;
            }
        }
        __syncthreads();

        if (khalf == 0) {
#pragma unroll
            for (int nt = 0; nt < 3; nt++) {
                const float4 v = *reinterpret_cast<const float4*>(
                    &red[((mt * 3 + nt) * 32 + l) * 4]);
                acc[nt][0] += v.x; acc[nt][1] += v.y;
                acc[nt][2] += v.z; acc[nt][3] += v.w;
            }
            const float z0a = 1.f / (1.f + __expf(-(xz0.x + acc[0][0])));
            const float z0b = 1.f / (1.f + __expf(-(xz0.y + acc[0][1])));
            const float z1a = 1.f / (1.f + __expf(-(xz1.x + acc[0][2])));
            const float z1b = 1.f / (1.f + __expf(-(xz1.y + acc[0][3])));
            const float r0a = 1.f / (1.f + __expf(-(xr0.x + acc[1][0])));
            const float r0b = 1.f / (1.f + __expf(-(xr0.y + acc[1][1])));
            const float r1a = 1.f / (1.f + __expf(-(xr1.x + acc[1][2])));
            const float r1b = 1.f / (1.f + __expf(-(xr1.y + acc[1][3])));
            const float g0a = tanhf(xg0.x + r0a * acc[2][0]);
            const float g0b = tanhf(xg0.y + r0b * acc[2][1]);
            const float g1a = tanhf(xg1.x + r1a * acc[2][2]);
            const float g1b = tanhf(xg1.y + r1b * acc[2][3]);
            const float h0a = (1.f - z0a) * g0a + z0a * hp0.x;
            const float h0b = (1.f - z0b) * g0b + z0b * hp0.y;
            const float h1a = (1.f - z1a) * g1a + z1a * hp1.x;
            const float h1b = (1.f - z1b) * g1b + z1b * hp1.y;
            hp0 = make_float2(h0a, h0b);
            hp1 = make_float2(h1a, h1b);

            // cross-block dependency stores FIRST (fp16 hi/lo)
            *reinterpret_cast<uint2*>(&hbn[n0 * 512 + wkt * 16 + wtq * 4 + wsl]) =
                make_uint2(packh(h0b, h0a), packh(hres(h0b), hres(h0a)));
            *reinterpret_cast<uint2*>(&hbn[n1 * 512 + wkt * 16 + wtq * 4 + wsl]) =
                make_uint2(packh(h1b, h1a), packh(hres(h1b), hres(h1a)));

            const int t_out = dir ? (TT - 1 - s) : s;
            *reinterpret_cast<float2*>(
                &out[((size_t)n0 * TT + t_out) * (2 * HH) + dir * HH + jA]) =
                make_float2(h0a, h0b);
            *reinterpret_cast<float2*>(
                &out[((size_t)n1 * TT + t_out) * (2 * HH) + dir * HH + jA]) =
                make_float2(h1a, h1b);

            if (s + 1 < TT) {
                const float* b0 = &xmd[((size_t)n0 * TT + (s + 1)) * G3 + jA];
                const float* b1 = &xmd[((size_t)n1 * TT + (s + 1)) * G3 + jA];
                xz0 = __ldg((const float2*)(b0));
                xr0 = __ldg((const float2*)(b0 + HH));
                xg0 = __ldg((const float2*)(b0 + 2 * HH));
                xz1 = __ldg((const float2*)(b1));
                xr1 = __ldg((const float2*)(b1 + HH));
                xg1 = __ldg((const float2*)(b1 + 2 * HH));
            }
        }

        __syncthreads();
        if (t == 0) {
            unsigned old;
            asm volatile("atom.add.release.gpu.u32 %0, [%1], 1;"
                         : "=r"(old) : "l"(&g_arrive[dir]) : "memory");
            const unsigned target = 64u * (unsigned)(s + 1);
            unsigned cur;
            do {
                asm volatile("ld.acquire.gpu.u32 %0, [%1];"
                             : "=r"(cur) : "l"(&g_arrive[dir]) : "memory");
            } while (cur < target);
        }
        __syncthreads();
    }
}

// -----------------------------------------------------------------------------
// Launch
// -----------------------------------------------------------------------------
extern "C" void kernel_launch(void* const* d_in, const int* in_sizes, int n_in,
                              void* d_out, int out_size)
{
    (void)in_sizes; (void)n_in; (void)out_size;
    const float* x   = (const float*)d_in[0];
    const float* Wxf = (const float*)d_in[1];
    const float* Whf = (const float*)d_in[2];
    const float* bf  = (const float*)d_in[3];
    const float* Wxb = (const float*)d_in[4];
    const float* Whb = (const float*)d_in[5];
    const float* bb  = (const float*)d_in[6];
    float* out = (float*)d_out;

    float* xm;
    unsigned* hbf;
    cudaGetSymbolAddress((void**)&xm, g_xm);
    cudaGetSymbolAddress((void**)&hbf, g_hbf);

    cudaFuncSetAttribute(gru_persist_mma_kernel,
                         cudaFuncAttributeMaxDynamicSharedMemorySize, PMMA_SMEM);

    // 1) h fp16 buffers = 0, barrier counters = 0
    init_kernel<<<128, 256>>>(hbf);

    // 2) input projections: fp16 MMA 2-pass + ldmatrix, pipelined
    sgemm_xm_f16_kernel<<<dim3(12, 256, 2), 256>>>(x, Wxf, Wxb, bf, bb, xm);

    // 3) persistent recurrence (fp16 2-pass, depth-4 pipelined h loads)
    gru_persist_mma_kernel<<<dim3(64, 2), 256, PMMA_SMEM>>>(
        Whf, Whb, xm, hbf, out);
}

// round 13
// speedup vs baseline: 1.3622x; 1.0408x over previous
#include <cuda_runtime.h>
#include <cuda_bf16.h>
#include <cuda_fp16.h>
#include <cstdint>

// Problem constants
#define NB   64      // batch
#define TT   512     // time steps
#define DD   512     // input dim
#define HH   512     // hidden dim
#define G3   1536    // 3*H

// Scratch (device globals: allocation-free)
__device__ float    g_xm[(size_t)2 * NB * TT * G3];   // [dir][n][t][3H]
// fp16 h, fragment-ready layout: [dir][par][row(64)][kt(32)][tq(4)][4]
//   cell = { hi(k2), lo(k2), hi(k2+4), lo(k2+4) }  (fp16x2 each)
__device__ unsigned g_hbf[2 * 2 * 64 * 512];
__device__ unsigned g_arrive[2];                      // monotonic barrier counters

// ---- fp16 packing helpers (A-side hi/lo split; W is single fp16) ----
__device__ __forceinline__ unsigned packh(float odd_k, float even_k) {
    unsigned r;
    asm("cvt.rn.f16x2.f32 %0, %1, %2;" : "=r"(r) : "f"(odd_k), "f"(even_k));
    return r;
}
__device__ __forceinline__ float hres(float x) {
    return x - __half2float(__float2half_rn(x));
}
__device__ __forceinline__ void mma_f16(float* c, const unsigned* a,
                                        unsigned b0, unsigned b1) {
    asm volatile(
        "mma.sync.aligned.m16n8k16.row.col.f32.f16.f16.f32 "
        "{%0,%1,%2,%3}, {%4,%5,%6,%7}, {%8,%9}, {%0,%1,%2,%3};"
        : "+f"(c[0]), "+f"(c[1]), "+f"(c[2]), "+f"(c[3])
        : "r"(a[0]), "r"(a[1]), "r"(a[2]), "r"(a[3]), "r"(b0), "r"(b1));
}
__device__ __forceinline__ void ldsm_x4(unsigned& r0, unsigned& r1,
                                        unsigned& r2, unsigned& r3, unsigned sa) {
    asm volatile("ldmatrix.sync.aligned.m8n8.x4.shared.b16 {%0,%1,%2,%3}, [%4];"
                 : "=r"(r0), "=r"(r1), "=r"(r2), "=r"(r3) : "r"(sa));
}
__device__ __forceinline__ unsigned sm32(const void* p) {
    return (unsigned)__cvta_generic_to_shared(p);
}

// -----------------------------------------------------------------------------
// Init: zero fp16 h buffers + barrier counters
// -----------------------------------------------------------------------------
__global__ void init_kernel(unsigned* hbf) {
    int i = blockIdx.x * blockDim.x + threadIdx.x;   // 32768 uint4s
    reinterpret_cast<uint4*>(hbf)[i] = make_uint4(0u, 0u, 0u, 0u);
    if (i == 0) { g_arrive[0] = 0; g_arrive[1] = 0; }
}

// -----------------------------------------------------------------------------
// Input projection GEMM: fp16 MMA, 2-pass A-side hi/lo split, ldmatrix loads.
// (identical to R12 — proven)
// -----------------------------------------------------------------------------
#define ARS 12

__global__ __launch_bounds__(256, 2) void sgemm_xm_f16_kernel(
    const float* __restrict__ x,
    const float* __restrict__ Wx_f, const float* __restrict__ Wx_b,
    const float* __restrict__ b_f,  const float* __restrict__ b_b,
    float* __restrict__ xm)
{
    const int dir = blockIdx.z;
    const float* __restrict__ Wx   = dir ? Wx_b : Wx_f;
    const float* __restrict__ bias = dir ? b_b  : b_f;
    float* __restrict__ C = xm + (size_t)dir * (NB * TT) * G3;

    __shared__ __align__(16) unsigned AH[128 * ARS];
    __shared__ __align__(16) unsigned AL[128 * ARS];
    __shared__ __align__(16) unsigned BH[128 * ARS];

    const int t = threadIdx.x;
    const int w = t >> 5;
    const int l = t & 31;
    const int warp_m = w >> 1;
    const int warp_n = w & 1;
    const int gid = l >> 2;
    const int tig = l & 3;

    const int mBase = blockIdx.y * 128;
    const int jBase = blockIdx.x * 128;

    const int aM  = t & 127;
    const int aKg = (t >> 7) * 8;
    const int am  = mBase + aM;
    const int an  = am >> 9;
    const int at0 = am & 511;
    const int ats = dir ? (TT - 1 - at0) : at0;
    const float* __restrict__ aPtr = x + ((size_t)an * TT + ats) * DD + aKg;
    const int aCol = aKg >> 1;

    const int bKp = t & 7;
    const int bN  = (t >> 3) * 4;
    const float* __restrict__ bPtr = Wx + (size_t)(2 * bKp) * G3 + jBase + bN;

    unsigned aAdH[2], aAdL[2], bAdH[4];
    {
        const int rowA = warp_m * 32 + (l & 7) + 8 * ((l >> 3) & 1);
        const int chA  = l >> 4;
#pragma unroll
        for (int mt = 0; mt < 2; mt++) {
            const int r = rowA + mt * 16;
            aAdH[mt] = sm32(&AH[r * ARS + chA * 4]);
            aAdL[mt] = sm32(&AL[r * ARS + chA * 4]);
        }
        const int rowB = warp_n * 64 + (l & 7) + 8 * ((l >> 4) & 1);
        const int chB  = (l >> 3) & 1;
#pragma unroll
        for (int np = 0; np < 4; np++) {
            const int n = rowB + np * 16;
            bAdH[np] = sm32(&BH[n * ARS + chB * 4]);
        }
    }

    float acc[2][8][4];
#pragma unroll
    for (int mt = 0; mt < 2; mt++)
#pragma unroll
        for (int nt = 0; nt < 8; nt++)
#pragma unroll
            for (int r = 0; r < 4; r++) acc[mt][nt][r] = 0.f;

    float4 av0 = *reinterpret_cast<const float4*>(aPtr);
    float4 av1 = *reinterpret_cast<const float4*>(aPtr + 4);
    float4 be  = *reinterpret_cast<const float4*>(bPtr);
    float4 bo  = *reinterpret_cast<const float4*>(bPtr + G3);

    for (int k0 = 0; k0 < DD; k0 += 16) {
        {
            uint4 hh, ll;
            hh.x = packh(av0.y, av0.x); hh.y = packh(av0.w, av0.z);
            hh.z = packh(av1.y, av1.x); hh.w = packh(av1.w, av1.z);
            ll.x = packh(hres(av0.y), hres(av0.x));
            ll.y = packh(hres(av0.w), hres(av0.z));
            ll.z = packh(hres(av1.y), hres(av1.x));
            ll.w = packh(hres(av1.w), hres(av1.z));
            *reinterpret_cast<uint4*>(&AH[aM * ARS + aCol]) = hh;
            *reinterpret_cast<uint4*>(&AL[aM * ARS + aCol]) = ll;
        }
        {
            const float ee[4] = {be.x, be.y, be.z, be.w};
            const float oo[4] = {bo.x, bo.y, bo.z, bo.w};
#pragma unroll
            for (int c = 0; c < 4; c++)
                BH[(bN + c) * ARS + bKp] = packh(oo[c], ee[c]);
        }
        __syncthreads();

        if (k0 + 16 < DD) {
            av0 = *reinterpret_cast<const float4*>(aPtr + k0 + 16);
            av1 = *reinterpret_cast<const float4*>(aPtr + k0 + 20);
            be  = *reinterpret_cast<const float4*>(bPtr + (size_t)(k0 + 16) * G3);
            bo  = *reinterpret_cast<const float4*>(bPtr + (size_t)(k0 + 16) * G3 + G3);
        }

        unsigned ahi[2][4], alo[2][4];
#pragma unroll
        for (int mt = 0; mt < 2; mt++) {
            ldsm_x4(ahi[mt][0], ahi[mt][1], ahi[mt][2], ahi[mt][3], aAdH[mt]);
            ldsm_x4(alo[mt][0], alo[mt][1], alo[mt][2], alo[mt][3], aAdL[mt]);
        }
#pragma unroll
        for (int np = 0; np < 4; np++) {
            unsigned bh[4];
            ldsm_x4(bh[0], bh[1], bh[2], bh[3], bAdH[np]);
#pragma unroll
            for (int tile = 0; tile < 2; tile++) {
                const int nt = np * 2 + tile;
#pragma unroll
                for (int mt = 0; mt < 2; mt++) {
                    mma_f16(acc[mt][nt], ahi[mt], bh[2 * tile], bh[2 * tile + 1]);
                    mma_f16(acc[mt][nt], alo[mt], bh[2 * tile], bh[2 * tile + 1]);
                }
            }
        }
        __syncthreads();
    }

#pragma unroll
    for (int mt = 0; mt < 2; mt++) {
        const int m0 = mBase + warp_m * 32 + mt * 16 + gid;
        const int m1 = m0 + 8;
#pragma unroll
        for (int nt = 0; nt < 8; nt++) {
            const int col = jBase + warp_n * 64 + nt * 8 + tig * 2;
            const float2 bv = *reinterpret_cast<const float2*>(&bias[col]);
            float2 o0, o1;
            o0.x = acc[mt][nt][0] + bv.x;  o0.y = acc[mt][nt][1] + bv.y;
            o1.x = acc[mt][nt][2] + bv.x;  o1.y = acc[mt][nt][3] + bv.y;
            *reinterpret_cast<float2*>(&C[(size_t)m0 * G3 + col]) = o0;
            *reinterpret_cast<float2*>(&C[(size_t)m1 * G3 + col]) = o1;
        }
    }
}

// -----------------------------------------------------------------------------
// Persistent recurrence, occupancy-2 version.
// Grid dim3(64, 2, 2): x=j-block(8 cols), y=mhalf(32 rows), z=dir.
// 128 threads (4 warps: mt = w&1, khalf = w>>1). 27KB SMEM -> 2 blocks/SM;
// co-resident blocks from independent barrier domains overlap each other's
// serial phases (barrier wait, exchange, gates) with MMA work.
// Barrier: 128 arrivals per dir per step.
// -----------------------------------------------------------------------------
#define BFRAG_UINTS  (32 * 3 * 32 * 2)           // 6144 -> 24KB
#define REDF         (6 * 32 * 4)                // 768 floats -> 3KB
#define PMMA_SMEM    ((BFRAG_UINTS + REDF) * 4)  // 27648 B
#define HB_PP        32768                       // uints per (dir,parity)

__global__ __launch_bounds__(128, 2) void gru_persist_mma_kernel(
    const float* __restrict__ Wh_f, const float* __restrict__ Wh_b,
    const float* __restrict__ xm, unsigned* __restrict__ hbf,
    float* __restrict__ out)
{
    extern __shared__ unsigned smu[];
    unsigned* bfr = smu;                         // [kt][gate][lane][2]
    float* red = reinterpret_cast<float*>(smu + BFRAG_UINTS);

    const int dir   = blockIdx.z;
    const int mhalf = blockIdx.y;
    const int j0    = blockIdx.x * 8;
    const float* __restrict__ Wh = dir ? Wh_b : Wh_f;

    const int t  = threadIdx.x;
    const int w  = t >> 5;
    const int l  = t & 31;
    const int g  = l >> 2;
    const int tq = l & 3;
    const int mt    = w & 1;
    const int khalf = w >> 1;

    // ---- fill W B-fragments once (fp16, single pass) ----
    for (int idx = t; idx < 24 * 256; idx += 128) {
        const int c_loc = idx >> 8;
        const int k2    = idx & 255;
        const int gate  = c_loc >> 3;
        const int jj    = c_loc & 7;
        const int col   = gate * HH + j0 + jj;
        const float e = Wh[(size_t)(2 * k2) * G3 + col];
        const float o = Wh[(size_t)(2 * k2 + 1) * G3 + col];
        const int kt = k2 >> 3;
        const int pp = k2 & 7;
        const int rr = pp >> 2;
        const int ts = pp & 3;
        const int off2 = ((kt * 3 + gate) * 32 + jj * 4 + ts) * 2;
        bfr[off2 + rr] = packh(o, e);
    }
    __syncthreads();

    const int row0 = mhalf * 32 + mt * 16 + g;
    const int row1 = row0 + 8;
    const int n0 = row0, n1 = row1;
    const int jA  = j0 + 2 * tq;
    const int k2g = (j0 >> 1) + tq;
    const int wkt = k2g >> 3;
    const int wpp = k2g & 7;
    const int wtq = wpp & 3;
    const int wsl = (wpp >> 2) * 2;
    const float* xmd = xm + (size_t)dir * (NB * TT) * G3;

    float2 xz0, xr0, xg0, xz1, xr1, xg1;
    float2 hp0 = make_float2(0.f, 0.f), hp1 = make_float2(0.f, 0.f);
    if (khalf == 0) {
        const float* b0 = &xmd[((size_t)n0 * TT + 0) * G3 + jA];
        const float* b1 = &xmd[((size_t)n1 * TT + 0) * G3 + jA];
        xz0 = __ldg((const float2*)(b0));
        xr0 = __ldg((const float2*)(b0 + HH));
        xg0 = __ldg((const float2*)(b0 + 2 * HH));
        xz1 = __ldg((const float2*)(b1));
        xr1 = __ldg((const float2*)(b1 + HH));
        xg1 = __ldg((const float2*)(b1 + 2 * HH));
    }

    const int ktb = khalf * 16;

    for (int s = 0; s < TT; s++) {
        const int p = s & 1;
        const unsigned* __restrict__ hb  = hbf + ((size_t)dir * 2 + p)       * HB_PP;
        unsigned*       __restrict__ hbn = hbf + ((size_t)dir * 2 + (p ^ 1)) * HB_PP;

        float acc[3][4];
#pragma unroll
        for (int nt = 0; nt < 3; nt++)
#pragma unroll
            for (int r = 0; r < 4; r++) acc[nt][r] = 0.f;

        uint4 v0[4], v1[4];
#pragma unroll
        for (int pf = 0; pf < 4; pf++) {
            v0[pf] = __ldg(reinterpret_cast<const uint4*>(
                &hb[row0 * 512 + (ktb + pf) * 16 + tq * 4]));
            v1[pf] = __ldg(reinterpret_cast<const uint4*>(
                &hb[row1 * 512 + (ktb + pf) * 16 + tq * 4]));
        }
#pragma unroll
        for (int ki = 0; ki < 16; ki++) {
            const int kt  = ktb + ki;
            const int cur = ki & 3;
            unsigned aH[4], aL[4];
            aH[0] = v0[cur].x; aH[1] = v1[cur].x; aH[2] = v0[cur].z; aH[3] = v1[cur].z;
            aL[0] = v0[cur].y; aL[1] = v1[cur].y; aL[2] = v0[cur].w; aL[3] = v1[cur].w;
            if (ki < 12) {
                v0[cur] = __ldg(reinterpret_cast<const uint4*>(
                    &hb[row0 * 512 + (kt + 4) * 16 + tq * 4]));
                v1[cur] = __ldg(reinterpret_cast<const uint4*>(
                    &hb[row1 * 512 + (kt + 4) * 16 + tq * 4]));
            }
#pragma unroll
            for (int nt = 0; nt < 3; nt++) {
                const uint2 bb = *reinterpret_cast<const uint2*>(
                    &bfr[((kt * 3 + nt) * 32 + l) * 2]);
                mma_f16(acc[nt], aH, bb.x, bb.y);
                mma_f16(acc[nt], aL, bb.x, bb.y);
            }
        }

        // ---- split-K exchange (khalf1 -> red -> khalf0) ----
        if (khalf == 1) {
#pragma unroll
            for (int nt = 0; nt < 3; nt++) {
                float4 v = make_float4(acc[nt][0], acc[nt][1], acc[nt][2], acc[nt][3]);
                *reinterpret_cast<float4*>(&red[((mt * 3 + nt) * 32 + l) * 4]) = v;
            }
        }
        __syncthreads();

        if (khalf == 0) {
#pragma unroll
            for (int nt = 0; nt < 3; nt++) {
                const float4 v = *reinterpret_cast<const float4*>(
                    &red[((mt * 3 + nt) * 32 + l) * 4]);
                acc[nt][0] += v.x; acc[nt][1] += v.y;
                acc[nt][2] += v.z; acc[nt][3] += v.w;
            }
            const float z0a = 1.f / (1.f + __expf(-(xz0.x + acc[0][0])));
            const float z0b = 1.f / (1.f + __expf(-(xz0.y + acc[0][1])));
            const float z1a = 1.f / (1.f + __expf(-(xz1.x + acc[0][2])));
            const float z1b = 1.f / (1.f + __expf(-(xz1.y + acc[0][3])));
            const float r0a = 1.f / (1.f + __expf(-(xr0.x + acc[1][0])));
            const float r0b = 1.f / (1.f + __expf(-(xr0.y + acc[1][1])));
            const float r1a = 1.f / (1.f + __expf(-(xr1.x + acc[1][2])));
            const float r1b = 1.f / (1.f + __expf(-(xr1.y + acc[1][3])));
            const float g0a = tanhf(xg0.x + r0a * acc[2][0]);
            const float g0b = tanhf(xg0.y + r0b * acc[2][1]);
            const float g1a = tanhf(xg1.x + r1a * acc[2][2]);
            const float g1b = tanhf(xg1.y + r1b * acc[2][3]);
            const float h0a = (1.f - z0a) * g0a + z0a * hp0.x;
            const float h0b = (1.f - z0b) * g0b + z0b * hp0.y;
            const float h1a = (1.f - z1a) * g1a + z1a * hp1.x;
            const float h1b = (1.f - z1b) * g1b + z1b * hp1.y;
            hp0 = make_float2(h0a, h0b);
            hp1 = make_float2(h1a, h1b);

            // cross-block dependency stores FIRST (fp16 hi/lo)
            *reinterpret_cast<uint2*>(&hbn[n0 * 512 + wkt * 16 + wtq * 4 + wsl]) =
                make_uint2(packh(h0b, h0a), packh(hres(h0b), hres(h0a)));
            *reinterpret_cast<uint2*>(&hbn[n1 * 512 + wkt * 16 + wtq * 4 + wsl]) =
                make_uint2(packh(h1b, h1a), packh(hres(h1b), hres(h1a)));

            const int t_out = dir ? (TT - 1 - s) : s;
            *reinterpret_cast<float2*>(
                &out[((size_t)n0 * TT + t_out) * (2 * HH) + dir * HH + jA]) =
                make_float2(h0a, h0b);
            *reinterpret_cast<float2*>(
                &out[((size_t)n1 * TT + t_out) * (2 * HH) + dir * HH + jA]) =
                make_float2(h1a, h1b);

            if (s + 1 < TT) {
                const float* b0 = &xmd[((size_t)n0 * TT + (s + 1)) * G3 + jA];
                const float* b1 = &xmd[((size_t)n1 * TT + (s + 1)) * G3 + jA];
                xz0 = __ldg((const float2*)(b0));
                xr0 = __ldg((const float2*)(b0 + HH));
                xg0 = __ldg((const float2*)(b0 + 2 * HH));
                xz1 = __ldg((const float2*)(b1));
                xr1 = __ldg((const float2*)(b1 + HH));
                xg1 = __ldg((const float2*)(b1 + 2 * HH));
            }
        }

        // ---- per-direction release/acquire barrier (128 blocks) ----
        __syncthreads();
        if (t == 0) {
            unsigned old;
            asm volatile("atom.add.release.gpu.u32 %0, [%1], 1;"
                         : "=r"(old) : "l"(&g_arrive[dir]) : "memory");
            const unsigned target = 128u * (unsigned)(s + 1);
            unsigned cur;
            do {
                asm volatile("ld.acquire.gpu.u32 %0, [%1];"
                             : "=r"(cur) : "l"(&g_arrive[dir]) : "memory");
            } while (cur < target);
        }
        __syncthreads();
    }
}

// -----------------------------------------------------------------------------
// Launch
// -----------------------------------------------------------------------------
extern "C" void kernel_launch(void* const* d_in, const int* in_sizes, int n_in,
                              void* d_out, int out_size)
{
    (void)in_sizes; (void)n_in; (void)out_size;
    const float* x   = (const float*)d_in[0];
    const float* Wxf = (const float*)d_in[1];
    const float* Whf = (const float*)d_in[2];
    const float* bf  = (const float*)d_in[3];
    const float* Wxb = (const float*)d_in[4];
    const float* Whb = (const float*)d_in[5];
    const float* bb  = (const float*)d_in[6];
    float* out = (float*)d_out;

    float* xm;
    unsigned* hbf;
    cudaGetSymbolAddress((void**)&xm, g_xm);
    cudaGetSymbolAddress((void**)&hbf, g_hbf);

    cudaFuncSetAttribute(gru_persist_mma_kernel,
                         cudaFuncAttributeMaxDynamicSharedMemorySize, PMMA_SMEM);

    // 1) h fp16 buffers = 0, barrier counters = 0
    init_kernel<<<128, 256>>>(hbf);

    // 2) input projections: fp16 MMA 2-pass + ldmatrix, pipelined
    sgemm_xm_f16_kernel<<<dim3(12, 256, 2), 256>>>(x, Wxf, Wxb, bf, bb, xm);

    // 3) persistent recurrence, occupancy-2 (256 blocks, 2/SM, overlapped
    //    barrier domains)
    gru_persist_mma_kernel<<<dim3(64, 2, 2), 128, PMMA_SMEM>>>(
        Whf, Whb, xm, hbf, out);
}